// round 2
// baseline (speedup 1.0000x reference)
#include <cuda_runtime.h>
#include <math.h>

#define LNUM 4
#define DIM 256
#define NH 8
#define MLP 1024
#define BATCH 8
#define SEQ 1024
#define HID 2048            // NH * DIM
#define ROWS (BATCH*SEQ)    // 8192
#define BH (BATCH*NH)       // 64

// ---------------- scratch (device globals; no allocation allowed) ----------------
__device__ float g_h[ROWS*DIM];            // LN output            8 MB
__device__ float g_q[BH*SEQ*DIM];          // q [b,h,n,d]          8 MB
__device__ float g_k[BH*SEQ*DIM];          // k                    8 MB
__device__ float g_v[BH*SEQ*DIM];          // v                    8 MB
__device__ float g_s[(size_t)BH*SEQ*SEQ];  // scores             256 MB
__device__ float g_o[(size_t)ROWS*HID];    // attn out [b,n,h*d]  64 MB
__device__ float g_m[ROWS*MLP];            // mlp hidden          32 MB

// ---------------- LayerNorm: one block (256 thr) per row of 256 ----------------
__global__ void ln_kernel(const float* __restrict__ x, const float* __restrict__ g,
                          const float* __restrict__ b, float* __restrict__ out)
{
    __shared__ float red0[8], red1[8];
    __shared__ float mv0, mv1;
    int row = blockIdx.x;
    int t = threadIdx.x;
    float val = x[(long)row*DIM + t];
    float s1 = val, s2 = val*val;
    #pragma unroll
    for (int o = 16; o > 0; o >>= 1) {
        s1 += __shfl_xor_sync(0xffffffffu, s1, o);
        s2 += __shfl_xor_sync(0xffffffffu, s2, o);
    }
    if ((t & 31) == 0) { red0[t>>5] = s1; red1[t>>5] = s2; }
    __syncthreads();
    if (t == 0) {
        float a = 0.f, c = 0.f;
        #pragma unroll
        for (int i = 0; i < 8; i++) { a += red0[i]; c += red1[i]; }
        float m = a * (1.0f/DIM);
        mv0 = m;
        mv1 = rsqrtf(c * (1.0f/DIM) - m*m + 1e-5f);
    }
    __syncthreads();
    out[(long)row*DIM + t] = (val - mv0) * mv1 * g[t] + b[t];
}

// ---------------- Softmax over rows of 1024, then /16 (post-softmax scale) ------
__global__ void softmax_kernel(float* __restrict__ s)
{
    __shared__ float red[8];
    __shared__ float bc;
    long base = (long)blockIdx.x * SEQ;
    int t = threadIdx.x;
    float4 v = *(const float4*)(s + base + t*4);
    float mx = fmaxf(fmaxf(v.x, v.y), fmaxf(v.z, v.w));
    #pragma unroll
    for (int o = 16; o > 0; o >>= 1) mx = fmaxf(mx, __shfl_xor_sync(0xffffffffu, mx, o));
    if ((t & 31) == 0) red[t>>5] = mx;
    __syncthreads();
    if (t == 0) {
        float m = red[0];
        #pragma unroll
        for (int i = 1; i < 8; i++) m = fmaxf(m, red[i]);
        bc = m;
    }
    __syncthreads();
    float m = bc;
    __syncthreads();
    v.x = expf(v.x - m); v.y = expf(v.y - m); v.z = expf(v.z - m); v.w = expf(v.w - m);
    float sm = v.x + v.y + v.z + v.w;
    #pragma unroll
    for (int o = 16; o > 0; o >>= 1) sm += __shfl_xor_sync(0xffffffffu, sm, o);
    if ((t & 31) == 0) red[t>>5] = sm;
    __syncthreads();
    if (t == 0) {
        float a = 0.f;
        #pragma unroll
        for (int i = 0; i < 8; i++) a += red[i];
        bc = a;
    }
    __syncthreads();
    float inv = 1.0f / (bc * 16.0f);   // post-softmax /sqrt(256)
    v.x *= inv; v.y *= inv; v.z *= inv; v.w *= inv;
    *(float4*)(s + base + t*4) = v;
}

// ---------------- Generic 128x128x8 SGEMM, 256 threads, 8x8/thread --------------
// A: row-major [M,K], lda=K (always). B: NN -> row-major [K,N] ldb=N;
//                                     NT -> row-major [N,K] ldb=K (C=A*B^T).
// All of M,N divisible by 128 and K by 8 for every call (verified statically).
enum { EPI_STORE = 0, EPI_QKV = 1, EPI_BIAS_RES = 2, EPI_BIAS_GELU = 3, EPI_OSCAT = 4 };

template<int EPI, bool TB>
__global__ __launch_bounds__(256)
void gemm_k(const float* __restrict__ A, const float* __restrict__ Bm,
            const float* __restrict__ bias, float* __restrict__ Cp,
            float* __restrict__ P1, float* __restrict__ P2,
            int Mr, int Nc, int K,
            long strideA, long strideB, long strideC)
{
    __shared__ float As[8][128];
    __shared__ float Bs[8][128];

    int z = blockIdx.z;
    const float* Ab = A  + (long)z * strideA;
    const float* Bb = Bm + (long)z * strideB;
    int m0 = blockIdx.y * 128;
    int n0 = blockIdx.x * 128;
    int t  = threadIdx.x;

    int arow = t >> 1, ac4 = (t & 1) * 4;     // A / NT-B loader: 128 rows x (2x4) cols
    int brow = t >> 5, bc4 = (t & 31) * 4;    // NN-B loader: 8 rows x (32x4) cols
    int tx = t & 15, ty = t >> 4;

    float acc[8][8];
    #pragma unroll
    for (int i = 0; i < 8; i++)
        #pragma unroll
        for (int j = 0; j < 8; j++) acc[i][j] = 0.f;

    for (int k0 = 0; k0 < K; k0 += 8) {
        float4 av = *(const float4*)(Ab + (long)(m0 + arow)*K + k0 + ac4);
        As[ac4+0][arow] = av.x; As[ac4+1][arow] = av.y;
        As[ac4+2][arow] = av.z; As[ac4+3][arow] = av.w;
        if (!TB) {
            float4 bv = *(const float4*)(Bb + (long)(k0 + brow)*Nc + n0 + bc4);
            *(float4*)&Bs[brow][bc4] = bv;
        } else {
            float4 bv = *(const float4*)(Bb + (long)(n0 + arow)*K + k0 + ac4);
            Bs[ac4+0][arow] = bv.x; Bs[ac4+1][arow] = bv.y;
            Bs[ac4+2][arow] = bv.z; Bs[ac4+3][arow] = bv.w;
        }
        __syncthreads();
        #pragma unroll
        for (int kk = 0; kk < 8; kk++) {
            float ra[8], rb[8];
            *(float4*)&ra[0] = *(const float4*)&As[kk][ty*8];
            *(float4*)&ra[4] = *(const float4*)&As[kk][ty*8 + 4];
            *(float4*)&rb[0] = *(const float4*)&Bs[kk][tx*8];
            *(float4*)&rb[4] = *(const float4*)&Bs[kk][tx*8 + 4];
            #pragma unroll
            for (int i = 0; i < 8; i++)
                #pragma unroll
                for (int j = 0; j < 8; j++)
                    acc[i][j] = fmaf(ra[i], rb[j], acc[i][j]);
        }
        __syncthreads();
    }

    #pragma unroll
    for (int i = 0; i < 8; i++) {
        int row = m0 + ty*8 + i;
        #pragma unroll
        for (int j = 0; j < 8; j++) {
            int col = n0 + tx*8 + j;
            float v = acc[i][j];
            if (EPI == EPI_STORE) {
                Cp[(long)z*strideC + (long)row*Nc + col] = v;
            } else if (EPI == EPI_QKV) {
                v += bias[col];
                int s  = col % 3;
                int dc = (col / 3) & (DIM - 1);
                int h  = col / (3*DIM);
                int b  = row >> 10, n = row & (SEQ - 1);
                long idx = (((long)(b*NH + h))*SEQ + n)*DIM + dc;
                float* dst = (s == 0) ? Cp : ((s == 1) ? P1 : P2);
                dst[idx] = v;
            } else if (EPI == EPI_BIAS_RES) {
                Cp[(long)row*Nc + col] += v + bias[col];
            } else if (EPI == EPI_BIAS_GELU) {
                float u = v + bias[col];
                Cp[(long)row*Nc + col] = 0.5f * u * (1.0f + erff(u * 0.70710678118654752f));
            } else { // EPI_OSCAT: z = b*NH+h, write [b, row, h*DIM+col]
                int b = z >> 3, h = z & 7;
                Cp[((long)(b*SEQ + row))*HID + h*DIM + col] = v;
            }
        }
    }
}

// ---------------- host orchestration ----------------
extern "C" void kernel_launch(void* const* d_in, const int* in_sizes, int n_in,
                              void* d_out, int out_size)
{
    const float* x_in  = (const float*)d_in[0];
    const float* ln1_g = (const float*)d_in[1];
    const float* ln1_b = (const float*)d_in[2];
    const float* qkv_w = (const float*)d_in[3];
    const float* qkv_b = (const float*)d_in[4];
    const float* proj_w= (const float*)d_in[5];
    const float* proj_b= (const float*)d_in[6];
    const float* ln2_g = (const float*)d_in[7];
    const float* ln2_b = (const float*)d_in[8];
    const float* w1    = (const float*)d_in[9];
    const float* b1    = (const float*)d_in[10];
    const float* w2    = (const float*)d_in[11];
    const float* b2    = (const float*)d_in[12];
    float* out = (float*)d_out;

    float *h, *q, *k, *v, *s, *o, *mh;
    cudaGetSymbolAddress((void**)&h,  g_h);
    cudaGetSymbolAddress((void**)&q,  g_q);
    cudaGetSymbolAddress((void**)&k,  g_k);
    cudaGetSymbolAddress((void**)&v,  g_v);
    cudaGetSymbolAddress((void**)&s,  g_s);
    cudaGetSymbolAddress((void**)&o,  g_o);
    cudaGetSymbolAddress((void**)&mh, g_m);

    cudaMemcpyAsync(out, x_in, sizeof(float)*(size_t)ROWS*DIM, cudaMemcpyDeviceToDevice);

    for (int i = 0; i < LNUM; i++) {
        // LN1
        ln_kernel<<<ROWS, 256>>>(out, ln1_g + i*DIM, ln1_b + i*DIM, h);
        // QKV: [8192,256] x [256,6144] -> scatter q/k/v [b,h,n,d]
        gemm_k<EPI_QKV, false><<<dim3(3*HID/128, ROWS/128, 1), 256>>>(
            h, qkv_w + (long)i*DIM*3*HID, qkv_b + (long)i*3*HID,
            q, k, v, ROWS, 3*HID, DIM, 0, 0, 0);
        // scores = q @ k^T, batched over 64 (b,h)
        gemm_k<EPI_STORE, true><<<dim3(SEQ/128, SEQ/128, BH), 256>>>(
            q, k, nullptr, s, nullptr, nullptr,
            SEQ, SEQ, DIM, (long)SEQ*DIM, (long)SEQ*DIM, (long)SEQ*SEQ);
        // softmax + /16
        softmax_kernel<<<BH*SEQ, 256>>>(s);
        // o = attn @ v, batched; scatter into [b,n,h*d]
        gemm_k<EPI_OSCAT, false><<<dim3(DIM/128, SEQ/128, BH), 256>>>(
            s, v, nullptr, o, nullptr, nullptr,
            SEQ, DIM, SEQ, (long)SEQ*SEQ, (long)SEQ*DIM, 0);
        // x += o @ proj_w + proj_b
        gemm_k<EPI_BIAS_RES, false><<<dim3(DIM/128, ROWS/128, 1), 256>>>(
            o, proj_w + (long)i*HID*DIM, proj_b + (long)i*DIM,
            out, nullptr, nullptr, ROWS, DIM, HID, 0, 0, 0);
        // LN2
        ln_kernel<<<ROWS, 256>>>(out, ln2_g + i*DIM, ln2_b + i*DIM, h);
        // mlp hidden = gelu(h @ w1 + b1)
        gemm_k<EPI_BIAS_GELU, false><<<dim3(MLP/128, ROWS/128, 1), 256>>>(
            h, w1 + (long)i*DIM*MLP, b1 + (long)i*MLP,
            mh, nullptr, nullptr, ROWS, MLP, DIM, 0, 0, 0);
        // x += mh @ w2 + b2
        gemm_k<EPI_BIAS_RES, false><<<dim3(DIM/128, ROWS/128, 1), 256>>>(
            mh, w2 + (long)i*MLP*DIM, b2 + (long)i*DIM,
            out, nullptr, nullptr, ROWS, DIM, MLP, 0, 0, 0);
    }
}

// round 3
// speedup vs baseline: 1.7958x; 1.7958x over previous
#include <cuda_runtime.h>
#include <math.h>

#define LNUM 4
#define DIM 256
#define NH 8
#define MLP 1024
#define BATCH 8
#define SEQ 1024
#define HID 2048            // NH * DIM
#define ROWS (BATCH*SEQ)    // 8192
#define BH (BATCH*NH)       // 64

// ---------------- scratch (device globals; no allocation allowed) ----------------
__device__ float g_h[ROWS*DIM];            // LN output            8 MB
__device__ float g_q[BH*SEQ*DIM];          // q [b,h,n,d]          8 MB
__device__ float g_k[BH*SEQ*DIM];          // k                    8 MB
__device__ float g_v[BH*SEQ*DIM];          // v                    8 MB
__device__ float g_s[(size_t)BH*SEQ*SEQ];  // scores             256 MB
__device__ float g_o[(size_t)ROWS*HID];    // attn out [b,n,h*d]  64 MB
__device__ float g_m[ROWS*MLP];            // mlp hidden          32 MB

// ---------------- LayerNorm: one block (256 thr) per row of 256 ----------------
__global__ void ln_kernel(const float* __restrict__ x, const float* __restrict__ g,
                          const float* __restrict__ b, float* __restrict__ out)
{
    __shared__ float red0[8], red1[8];
    __shared__ float mv0, mv1;
    int row = blockIdx.x;
    int t = threadIdx.x;
    float val = x[(long)row*DIM + t];
    float s1 = val, s2 = val*val;
    #pragma unroll
    for (int o = 16; o > 0; o >>= 1) {
        s1 += __shfl_xor_sync(0xffffffffu, s1, o);
        s2 += __shfl_xor_sync(0xffffffffu, s2, o);
    }
    if ((t & 31) == 0) { red0[t>>5] = s1; red1[t>>5] = s2; }
    __syncthreads();
    if (t == 0) {
        float a = 0.f, c = 0.f;
        #pragma unroll
        for (int i = 0; i < 8; i++) { a += red0[i]; c += red1[i]; }
        float m = a * (1.0f/DIM);
        mv0 = m;
        mv1 = rsqrtf(c * (1.0f/DIM) - m*m + 1e-5f);
    }
    __syncthreads();
    out[(long)row*DIM + t] = (val - mv0) * mv1 * g[t] + b[t];
}

// ---------------- Softmax over rows of 1024, then /16 (post-softmax scale) ------
__global__ void softmax_kernel(float* __restrict__ s)
{
    __shared__ float red[8];
    __shared__ float bc;
    long base = (long)blockIdx.x * SEQ;
    int t = threadIdx.x;
    float4 v = *(const float4*)(s + base + t*4);
    float mx = fmaxf(fmaxf(v.x, v.y), fmaxf(v.z, v.w));
    #pragma unroll
    for (int o = 16; o > 0; o >>= 1) mx = fmaxf(mx, __shfl_xor_sync(0xffffffffu, mx, o));
    if ((t & 31) == 0) red[t>>5] = mx;
    __syncthreads();
    if (t == 0) {
        float m = red[0];
        #pragma unroll
        for (int i = 1; i < 8; i++) m = fmaxf(m, red[i]);
        bc = m;
    }
    __syncthreads();
    float m = bc;
    __syncthreads();
    v.x = expf(v.x - m); v.y = expf(v.y - m); v.z = expf(v.z - m); v.w = expf(v.w - m);
    float sm = v.x + v.y + v.z + v.w;
    #pragma unroll
    for (int o = 16; o > 0; o >>= 1) sm += __shfl_xor_sync(0xffffffffu, sm, o);
    if ((t & 31) == 0) red[t>>5] = sm;
    __syncthreads();
    if (t == 0) {
        float a = 0.f;
        #pragma unroll
        for (int i = 0; i < 8; i++) a += red[i];
        bc = a;
    }
    __syncthreads();
    float inv = 1.0f / (bc * 16.0f);   // post-softmax /sqrt(256)
    v.x *= inv; v.y *= inv; v.z *= inv; v.w *= inv;
    *(float4*)(s + base + t*4) = v;
}

// ---------------- tf32 tensor-core GEMM: block 128x128, 4 warps of 64x64 --------
// A: row-major [M,K]. B: NN -> row-major [K,N]; NT -> row-major [N,K] (C=A*B^T).
// M%128==0, N%128==0, K%16==0 for all call sites.
enum { EPI_STORE = 0, EPI_QKV = 1, EPI_BIAS_RES = 2, EPI_BIAS_GELU = 3, EPI_OSCAT = 4 };

__device__ __forceinline__ float f2tf32(float x) {
    unsigned y;
    asm("cvt.rna.tf32.f32 %0, %1;" : "=r"(y) : "f"(x));
    return __uint_as_float(y);
}

__device__ __forceinline__ void mma_tf32(float* d, const float* a, const float* b) {
    asm volatile(
        "mma.sync.aligned.m16n8k8.row.col.f32.tf32.tf32.f32 "
        "{%0,%1,%2,%3}, {%4,%5,%6,%7}, {%8,%9}, {%0,%1,%2,%3};"
        : "+f"(d[0]), "+f"(d[1]), "+f"(d[2]), "+f"(d[3])
        : "r"(__float_as_uint(a[0])), "r"(__float_as_uint(a[1])),
          "r"(__float_as_uint(a[2])), "r"(__float_as_uint(a[3])),
          "r"(__float_as_uint(b[0])), "r"(__float_as_uint(b[1])));
}

#define SPAD 132   // smem row stride (words); makes fragment LDS conflict-free

template<int EPI, bool TB>
__global__ __launch_bounds__(128, 2)
void gemm_tc(const float* __restrict__ A, const float* __restrict__ Bm,
             const float* __restrict__ bias, float* __restrict__ Cp,
             float* __restrict__ P1, float* __restrict__ P2,
             int Nc, int K, long strideA, long strideB, long strideC)
{
    __shared__ float As[16][SPAD];   // [k][m]
    __shared__ float Bs[16][SPAD];   // [k][n]

    int z  = blockIdx.z;
    const float* Ab = A  + (long)z * strideA;
    const float* Bb = Bm + (long)z * strideB;
    int m0 = blockIdx.y * 128;
    int n0 = blockIdx.x * 128;
    int t    = threadIdx.x;
    int lane = t & 31;
    int warp = t >> 5;
    int wm = (warp & 1) * 64;   // warp row offset in block tile
    int wn = (warp >> 1) * 64;  // warp col offset
    int gid = lane >> 2;        // group id 0..7
    int tig = lane & 3;         // thread-in-group 0..3

    float acc[4][8][4];
    #pragma unroll
    for (int mt = 0; mt < 4; mt++)
        #pragma unroll
        for (int nt = 0; nt < 8; nt++)
            #pragma unroll
            for (int p = 0; p < 4; p++) acc[mt][nt][p] = 0.f;

    // B NN loader indices: 16 rows x 128 cols, 8 threads per row
    int br = t >> 3, bc = (t & 7) * 16;

    for (int k0 = 0; k0 < K; k0 += 16) {
        // --- load A tile 128x16, transpose into As[k][m], cvt to tf32 ---
        {
            const float* ap = Ab + (long)(m0 + t) * K + k0;
            #pragma unroll
            for (int j = 0; j < 4; j++) {
                float4 v = *(const float4*)(ap + 4*j);
                As[4*j+0][t] = f2tf32(v.x);
                As[4*j+1][t] = f2tf32(v.y);
                As[4*j+2][t] = f2tf32(v.z);
                As[4*j+3][t] = f2tf32(v.w);
            }
        }
        // --- load B tile ---
        if (!TB) {
            const float* bp = Bb + (long)(k0 + br) * Nc + n0 + bc;
            #pragma unroll
            for (int j = 0; j < 4; j++) {
                float4 v = *(const float4*)(bp + 4*j);
                Bs[br][bc+4*j+0] = f2tf32(v.x);
                Bs[br][bc+4*j+1] = f2tf32(v.y);
                Bs[br][bc+4*j+2] = f2tf32(v.z);
                Bs[br][bc+4*j+3] = f2tf32(v.w);
            }
        } else {
            const float* bp = Bb + (long)(n0 + t) * K + k0;
            #pragma unroll
            for (int j = 0; j < 4; j++) {
                float4 v = *(const float4*)(bp + 4*j);
                Bs[4*j+0][t] = f2tf32(v.x);
                Bs[4*j+1][t] = f2tf32(v.y);
                Bs[4*j+2][t] = f2tf32(v.z);
                Bs[4*j+3][t] = f2tf32(v.w);
            }
        }
        __syncthreads();

        #pragma unroll
        for (int kk = 0; kk < 16; kk += 8) {
            float af[4][4], bf[8][2];
            #pragma unroll
            for (int mt = 0; mt < 4; mt++) {
                int r = wm + mt*16 + gid;
                af[mt][0] = As[kk + tig    ][r];
                af[mt][1] = As[kk + tig    ][r + 8];
                af[mt][2] = As[kk + tig + 4][r];
                af[mt][3] = As[kk + tig + 4][r + 8];
            }
            #pragma unroll
            for (int nt = 0; nt < 8; nt++) {
                int c = wn + nt*8 + gid;
                bf[nt][0] = Bs[kk + tig    ][c];
                bf[nt][1] = Bs[kk + tig + 4][c];
            }
            #pragma unroll
            for (int mt = 0; mt < 4; mt++)
                #pragma unroll
                for (int nt = 0; nt < 8; nt++)
                    mma_tf32(acc[mt][nt], af[mt], bf[nt]);
        }
        __syncthreads();
    }

    // ---------------- epilogue ----------------
    #pragma unroll
    for (int mt = 0; mt < 4; mt++) {
        #pragma unroll
        for (int nt = 0; nt < 8; nt++) {
            #pragma unroll
            for (int p = 0; p < 4; p++) {
                int row = m0 + wm + mt*16 + gid + ((p >= 2) ? 8 : 0);
                int col = n0 + wn + nt*8 + 2*tig + (p & 1);
                float v = acc[mt][nt][p];
                if (EPI == EPI_STORE) {
                    Cp[(long)z*strideC + (long)row*Nc + col] = v;
                } else if (EPI == EPI_QKV) {
                    v += bias[col];
                    int s  = col % 3;
                    int dc = (col / 3) & (DIM - 1);
                    int h  = col / (3*DIM);
                    int b  = row >> 10, n = row & (SEQ - 1);
                    long idx = (((long)(b*NH + h))*SEQ + n)*DIM + dc;
                    float* dst = (s == 0) ? Cp : ((s == 1) ? P1 : P2);
                    dst[idx] = v;
                } else if (EPI == EPI_BIAS_RES) {
                    Cp[(long)row*Nc + col] += v + bias[col];
                } else if (EPI == EPI_BIAS_GELU) {
                    float u = v + bias[col];
                    Cp[(long)row*Nc + col] = 0.5f * u * (1.0f + erff(u * 0.70710678118654752f));
                } else { // EPI_OSCAT: z = b*NH+h, write [b, row, h*DIM+col]
                    int b = z >> 3, h = z & 7;
                    Cp[((long)(b*SEQ + row))*HID + h*DIM + col] = v;
                }
            }
        }
    }
}

// ---------------- host orchestration ----------------
extern "C" void kernel_launch(void* const* d_in, const int* in_sizes, int n_in,
                              void* d_out, int out_size)
{
    const float* x_in  = (const float*)d_in[0];
    const float* ln1_g = (const float*)d_in[1];
    const float* ln1_b = (const float*)d_in[2];
    const float* qkv_w = (const float*)d_in[3];
    const float* qkv_b = (const float*)d_in[4];
    const float* proj_w= (const float*)d_in[5];
    const float* proj_b= (const float*)d_in[6];
    const float* ln2_g = (const float*)d_in[7];
    const float* ln2_b = (const float*)d_in[8];
    const float* w1    = (const float*)d_in[9];
    const float* b1    = (const float*)d_in[10];
    const float* w2    = (const float*)d_in[11];
    const float* b2    = (const float*)d_in[12];
    float* out = (float*)d_out;

    float *h, *q, *k, *v, *s, *o, *mh;
    cudaGetSymbolAddress((void**)&h,  g_h);
    cudaGetSymbolAddress((void**)&q,  g_q);
    cudaGetSymbolAddress((void**)&k,  g_k);
    cudaGetSymbolAddress((void**)&v,  g_v);
    cudaGetSymbolAddress((void**)&s,  g_s);
    cudaGetSymbolAddress((void**)&o,  g_o);
    cudaGetSymbolAddress((void**)&mh, g_m);

    cudaMemcpyAsync(out, x_in, sizeof(float)*(size_t)ROWS*DIM, cudaMemcpyDeviceToDevice);

    for (int i = 0; i < LNUM; i++) {
        // LN1
        ln_kernel<<<ROWS, 256>>>(out, ln1_g + i*DIM, ln1_b + i*DIM, h);
        // QKV: [8192,256] x [256,6144] -> scatter q/k/v [b,h,n,d]
        gemm_tc<EPI_QKV, false><<<dim3(3*HID/128, ROWS/128, 1), 128>>>(
            h, qkv_w + (long)i*DIM*3*HID, qkv_b + (long)i*3*HID,
            q, k, v, 3*HID, DIM, 0, 0, 0);
        // scores = q @ k^T, batched over 64 (b,h)
        gemm_tc<EPI_STORE, true><<<dim3(SEQ/128, SEQ/128, BH), 128>>>(
            q, k, nullptr, s, nullptr, nullptr,
            SEQ, DIM, (long)SEQ*DIM, (long)SEQ*DIM, (long)SEQ*SEQ);
        // softmax + /16
        softmax_kernel<<<BH*SEQ, 256>>>(s);
        // o = attn @ v, batched; scatter into [b,n,h*d]
        gemm_tc<EPI_OSCAT, false><<<dim3(DIM/128, SEQ/128, BH), 128>>>(
            s, v, nullptr, o, nullptr, nullptr,
            DIM, SEQ, (long)SEQ*SEQ, (long)SEQ*DIM, 0);
        // x += o @ proj_w + proj_b
        gemm_tc<EPI_BIAS_RES, false><<<dim3(DIM/128, ROWS/128, 1), 128>>>(
            o, proj_w + (long)i*HID*DIM, proj_b + (long)i*DIM,
            out, nullptr, nullptr, DIM, HID, 0, 0, 0);
        // LN2
        ln_kernel<<<ROWS, 256>>>(out, ln2_g + i*DIM, ln2_b + i*DIM, h);
        // mlp hidden = gelu(h @ w1 + b1)
        gemm_tc<EPI_BIAS_GELU, false><<<dim3(MLP/128, ROWS/128, 1), 128>>>(
            h, w1 + (long)i*DIM*MLP, b1 + (long)i*MLP,
            mh, nullptr, nullptr, MLP, DIM, 0, 0, 0);
        // x += mh @ w2 + b2
        gemm_tc<EPI_BIAS_RES, false><<<dim3(DIM/128, ROWS/128, 1), 128>>>(
            mh, w2 + (long)i*MLP*DIM, b2 + (long)i*DIM,
            out, nullptr, nullptr, DIM, MLP, 0, 0, 0);
    }
}

// round 4
// speedup vs baseline: 2.2919x; 1.2762x over previous
#include <cuda_runtime.h>
#include <math.h>

#define LNUM 4
#define DIM 256
#define NH 8
#define MLP 1024
#define BATCH 8
#define SEQ 1024
#define HID 2048            // NH * DIM
#define ROWS (BATCH*SEQ)    // 8192
#define BH (BATCH*NH)       // 64

// ---------------- scratch (device globals; no allocation allowed) ----------------
__device__ float g_h[ROWS*DIM];            // LN output            8 MB
__device__ float g_q[BH*SEQ*DIM];          // q [b,h,n,d]          8 MB
__device__ float g_k[BH*SEQ*DIM];          // k                    8 MB
__device__ float g_v[BH*SEQ*DIM];          // v                    8 MB
__device__ float g_s[(size_t)BH*SEQ*SEQ];  // scores             256 MB
__device__ float g_o[(size_t)ROWS*HID];    // attn out [b,n,h*d]  64 MB
__device__ float g_m[ROWS*MLP];            // mlp hidden          32 MB
// tf32-rounded weights (rounded once per launch)
__device__ float g_qkvw[LNUM*DIM*3*HID];   // 25 MB
__device__ float g_projw[LNUM*HID*DIM];    // 8 MB
__device__ float g_w1[LNUM*DIM*MLP];       // 4 MB
__device__ float g_w2[LNUM*MLP*DIM];       // 4 MB

__device__ __forceinline__ float f2tf32(float x) {
    unsigned y;
    asm("cvt.rna.tf32.f32 %0, %1;" : "=r"(y) : "f"(x));
    return __uint_as_float(y);
}

// ---------------- weight rounding: fp32 -> tf32 (rna) ----------------
__global__ void cvt_tf32_kernel(const float4* __restrict__ src, float4* __restrict__ dst, int n4)
{
    int i = blockIdx.x * blockDim.x + threadIdx.x;
    int stride = gridDim.x * blockDim.x;
    for (; i < n4; i += stride) {
        float4 v = src[i];
        v.x = f2tf32(v.x); v.y = f2tf32(v.y); v.z = f2tf32(v.z); v.w = f2tf32(v.w);
        dst[i] = v;
    }
}

// ---------------- LayerNorm: one block (256 thr) per row of 256 ----------------
__global__ void ln_kernel(const float* __restrict__ x, const float* __restrict__ g,
                          const float* __restrict__ b, float* __restrict__ out)
{
    __shared__ float red0[8], red1[8];
    __shared__ float mv0, mv1;
    int row = blockIdx.x;
    int t = threadIdx.x;
    float val = x[(long)row*DIM + t];
    float s1 = val, s2 = val*val;
    #pragma unroll
    for (int o = 16; o > 0; o >>= 1) {
        s1 += __shfl_xor_sync(0xffffffffu, s1, o);
        s2 += __shfl_xor_sync(0xffffffffu, s2, o);
    }
    if ((t & 31) == 0) { red0[t>>5] = s1; red1[t>>5] = s2; }
    __syncthreads();
    if (t == 0) {
        float a = 0.f, c = 0.f;
        #pragma unroll
        for (int i = 0; i < 8; i++) { a += red0[i]; c += red1[i]; }
        float m = a * (1.0f/DIM);
        mv0 = m;
        mv1 = rsqrtf(c * (1.0f/DIM) - m*m + 1e-5f);
    }
    __syncthreads();
    out[(long)row*DIM + t] = f2tf32((val - mv0) * mv1 * g[t] + b[t]);
}

// ---------------- Softmax over rows of 1024, then /16, round to tf32 ------------
__global__ void softmax_kernel(float* __restrict__ s)
{
    __shared__ float red[8];
    __shared__ float bc;
    long base = (long)blockIdx.x * SEQ;
    int t = threadIdx.x;
    float4 v = *(const float4*)(s + base + t*4);
    float mx = fmaxf(fmaxf(v.x, v.y), fmaxf(v.z, v.w));
    #pragma unroll
    for (int o = 16; o > 0; o >>= 1) mx = fmaxf(mx, __shfl_xor_sync(0xffffffffu, mx, o));
    if ((t & 31) == 0) red[t>>5] = mx;
    __syncthreads();
    if (t == 0) {
        float m = red[0];
        #pragma unroll
        for (int i = 1; i < 8; i++) m = fmaxf(m, red[i]);
        bc = m;
    }
    __syncthreads();
    float m = bc;
    __syncthreads();
    v.x = expf(v.x - m); v.y = expf(v.y - m); v.z = expf(v.z - m); v.w = expf(v.w - m);
    float sm = v.x + v.y + v.z + v.w;
    #pragma unroll
    for (int o = 16; o > 0; o >>= 1) sm += __shfl_xor_sync(0xffffffffu, sm, o);
    if ((t & 31) == 0) red[t>>5] = sm;
    __syncthreads();
    if (t == 0) {
        float a = 0.f;
        #pragma unroll
        for (int i = 0; i < 8; i++) a += red[i];
        bc = a;
    }
    __syncthreads();
    float inv = 1.0f / (bc * 16.0f);   // post-softmax /sqrt(256)
    v.x = f2tf32(v.x * inv); v.y = f2tf32(v.y * inv);
    v.z = f2tf32(v.z * inv); v.w = f2tf32(v.w * inv);
    *(float4*)(s + base + t*4) = v;
}

// ---------------- tf32 tensor-core GEMM, cp.async double-buffered ----------------
// Block 128x128, 256 threads (8 warps), warp tile 32x64 (2 m-tiles x 8 n-tiles).
// A row-major [M,K]; B NN: [K,N]; B NT: [N,K] (C = A*B^T).
// All inputs pre-rounded to tf32. M,N %128==0, K%16==0.
enum { EPI_STORE = 0, EPI_QKV = 1, EPI_BIAS_RES = 2, EPI_BIAS_GELU = 3, EPI_OSCAT = 4 };

__device__ __forceinline__ void mma_tf32(float* d, const float* a, const float* b) {
    asm volatile(
        "mma.sync.aligned.m16n8k8.row.col.f32.tf32.tf32.f32 "
        "{%0,%1,%2,%3}, {%4,%5,%6,%7}, {%8,%9}, {%0,%1,%2,%3};"
        : "+f"(d[0]), "+f"(d[1]), "+f"(d[2]), "+f"(d[3])
        : "r"(__float_as_uint(a[0])), "r"(__float_as_uint(a[1])),
          "r"(__float_as_uint(a[2])), "r"(__float_as_uint(a[3])),
          "r"(__float_as_uint(b[0])), "r"(__float_as_uint(b[1])));
}

__device__ __forceinline__ void cpa16(unsigned d, const float* s) {
    asm volatile("cp.async.ca.shared.global [%0], [%1], 16;" :: "r"(d), "l"(s));
}

#define ASTRIDE 20    // [m][k] padded stride: frag LDS residues gid*20+tig cover all banks
#define BNSTRIDE 136  // [k][n] padded stride: residues tig*8+gid cover all banks
#define ASZ (128*ASTRIDE)

template<int EPI, bool TB>
__global__ __launch_bounds__(256, 1)
void gemm_tc(const float* __restrict__ A, const float* __restrict__ Bm,
             const float* __restrict__ bias, float* __restrict__ Cp,
             float* __restrict__ P1, float* __restrict__ P2,
             int Nc, int K, long strideA, long strideB, long strideC)
{
    constexpr int BSZ = TB ? 128*ASTRIDE : 16*BNSTRIDE;
    __shared__ float As[2][ASZ];
    __shared__ float Bs[2][BSZ];

    int z  = blockIdx.z;
    const float* Ab = A  + (long)z * strideA;
    const float* Bb = Bm + (long)z * strideB;
    int m0 = blockIdx.y * 128;
    int n0 = blockIdx.x * 128;
    int t    = threadIdx.x;
    int lane = t & 31;
    int warp = t >> 5;
    int wm = (warp >> 1) * 32;   // 4 warp-rows of 32
    int wn = (warp & 1) * 64;    // 2 warp-cols of 64
    int gid = lane >> 2;
    int tig = lane & 3;

    // loaders
    int ar = t >> 1, ac = (t & 1) * 8;        // A / TB-B: 128 rows x 16, 2 thr/row
    int bnr = t >> 4, bnc = (t & 15) * 8;     // NN-B: 16 rows x 128, 16 thr/row

    unsigned asb = (unsigned)__cvta_generic_to_shared(&As[0][0]);
    unsigned bsb = (unsigned)__cvta_generic_to_shared(&Bs[0][0]);

    float acc[2][8][4];
    #pragma unroll
    for (int mt = 0; mt < 2; mt++)
        #pragma unroll
        for (int nt = 0; nt < 8; nt++)
            #pragma unroll
            for (int p = 0; p < 4; p++) acc[mt][nt][p] = 0.f;

    const float* apg = Ab + (long)(m0 + ar)*K + ac;
    const float* bpg = TB ? (Bb + (long)(n0 + ar)*K + ac)
                          : (Bb + (long)bnr*Nc + n0 + bnc);
    unsigned ad0 = asb + (unsigned)(ar*ASTRIDE + ac)*4u;
    unsigned bd0 = TB ? (bsb + (unsigned)(ar*ASTRIDE + ac)*4u)
                      : (bsb + (unsigned)(bnr*BNSTRIDE + bnc)*4u);

    // prologue: stage 0 <- k0=0
    cpa16(ad0, apg);       cpa16(ad0 + 16, apg + 4);
    cpa16(bd0, bpg);       cpa16(bd0 + 16, bpg + 4);
    asm volatile("cp.async.commit_group;");

    int niter = K / 16;
    for (int iter = 0; iter < niter; iter++) {
        int s = iter & 1;
        if (iter + 1 < niter) {
            int k0 = (iter + 1) * 16;
            const float* ap = apg + k0;
            const float* bp = TB ? (bpg + k0) : (bpg + (long)k0*Nc);
            unsigned ad = ad0 + (unsigned)((s^1)*ASZ)*4u;
            unsigned bd = bd0 + (unsigned)((s^1)*BSZ)*4u;
            cpa16(ad, ap);      cpa16(ad + 16, ap + 4);
            cpa16(bd, bp);      cpa16(bd + 16, bp + 4);
            asm volatile("cp.async.commit_group;");
            asm volatile("cp.async.wait_group 1;");
        } else {
            asm volatile("cp.async.wait_group 0;");
        }
        __syncthreads();

        const float* Asb = &As[s][0];
        const float* Bsb = &Bs[s][0];
        #pragma unroll
        for (int kk = 0; kk < 16; kk += 8) {
            float af[2][4], bf[8][2];
            #pragma unroll
            for (int mt = 0; mt < 2; mt++) {
                int r = wm + mt*16 + gid;
                af[mt][0] = Asb[r*ASTRIDE + kk + tig];
                af[mt][1] = Asb[(r+8)*ASTRIDE + kk + tig];
                af[mt][2] = Asb[r*ASTRIDE + kk + tig + 4];
                af[mt][3] = Asb[(r+8)*ASTRIDE + kk + tig + 4];
            }
            #pragma unroll
            for (int nt = 0; nt < 8; nt++) {
                int c = wn + nt*8 + gid;
                if (TB) {
                    bf[nt][0] = Bsb[c*ASTRIDE + kk + tig];
                    bf[nt][1] = Bsb[c*ASTRIDE + kk + tig + 4];
                } else {
                    bf[nt][0] = Bsb[(kk + tig)*BNSTRIDE + c];
                    bf[nt][1] = Bsb[(kk + tig + 4)*BNSTRIDE + c];
                }
            }
            #pragma unroll
            for (int mt = 0; mt < 2; mt++)
                #pragma unroll
                for (int nt = 0; nt < 8; nt++)
                    mma_tf32(acc[mt][nt], af[mt], bf[nt]);
        }
        __syncthreads();
    }

    // ---------------- epilogue ----------------
    #pragma unroll
    for (int mt = 0; mt < 2; mt++) {
        #pragma unroll
        for (int nt = 0; nt < 8; nt++) {
            #pragma unroll
            for (int p = 0; p < 4; p++) {
                int row = m0 + wm + mt*16 + gid + ((p >= 2) ? 8 : 0);
                int col = n0 + wn + nt*8 + 2*tig + (p & 1);
                float v = acc[mt][nt][p];
                if (EPI == EPI_STORE) {
                    Cp[(long)z*strideC + (long)row*Nc + col] = v;
                } else if (EPI == EPI_QKV) {
                    v = f2tf32(v + bias[col]);
                    int s  = col % 3;
                    int dc = (col / 3) & (DIM - 1);
                    int h  = col / (3*DIM);
                    int b  = row >> 10, n = row & (SEQ - 1);
                    long idx = (((long)(b*NH + h))*SEQ + n)*DIM + dc;
                    float* dst = (s == 0) ? Cp : ((s == 1) ? P1 : P2);
                    dst[idx] = v;
                } else if (EPI == EPI_BIAS_RES) {
                    Cp[(long)row*Nc + col] += v + bias[col];
                } else if (EPI == EPI_BIAS_GELU) {
                    float u = v + bias[col];
                    Cp[(long)row*Nc + col] = f2tf32(0.5f * u * (1.0f + erff(u * 0.70710678118654752f)));
                } else { // EPI_OSCAT
                    int b = z >> 3, h = z & 7;
                    Cp[((long)(b*SEQ + row))*HID + h*DIM + col] = f2tf32(v);
                }
            }
        }
    }
}

// ---------------- host orchestration ----------------
extern "C" void kernel_launch(void* const* d_in, const int* in_sizes, int n_in,
                              void* d_out, int out_size)
{
    const float* x_in  = (const float*)d_in[0];
    const float* ln1_g = (const float*)d_in[1];
    const float* ln1_b = (const float*)d_in[2];
    const float* qkv_w = (const float*)d_in[3];
    const float* qkv_b = (const float*)d_in[4];
    const float* proj_w= (const float*)d_in[5];
    const float* proj_b= (const float*)d_in[6];
    const float* ln2_g = (const float*)d_in[7];
    const float* ln2_b = (const float*)d_in[8];
    const float* w1    = (const float*)d_in[9];
    const float* b1    = (const float*)d_in[10];
    const float* w2    = (const float*)d_in[11];
    const float* b2    = (const float*)d_in[12];
    float* out = (float*)d_out;

    float *h, *q, *k, *v, *s, *o, *mh, *rqkvw, *rprojw, *rw1, *rw2;
    cudaGetSymbolAddress((void**)&h,  g_h);
    cudaGetSymbolAddress((void**)&q,  g_q);
    cudaGetSymbolAddress((void**)&k,  g_k);
    cudaGetSymbolAddress((void**)&v,  g_v);
    cudaGetSymbolAddress((void**)&s,  g_s);
    cudaGetSymbolAddress((void**)&o,  g_o);
    cudaGetSymbolAddress((void**)&mh, g_m);
    cudaGetSymbolAddress((void**)&rqkvw, g_qkvw);
    cudaGetSymbolAddress((void**)&rprojw, g_projw);
    cudaGetSymbolAddress((void**)&rw1, g_w1);
    cudaGetSymbolAddress((void**)&rw2, g_w2);

    // round weights to tf32 once per launch
    cvt_tf32_kernel<<<2048, 256>>>((const float4*)qkv_w,  (float4*)rqkvw,  LNUM*DIM*3*HID/4);
    cvt_tf32_kernel<<<1024, 256>>>((const float4*)proj_w, (float4*)rprojw, LNUM*HID*DIM/4);
    cvt_tf32_kernel<<<512, 256>>>((const float4*)w1, (float4*)rw1, LNUM*DIM*MLP/4);
    cvt_tf32_kernel<<<512, 256>>>((const float4*)w2, (float4*)rw2, LNUM*MLP*DIM/4);

    cudaMemcpyAsync(out, x_in, sizeof(float)*(size_t)ROWS*DIM, cudaMemcpyDeviceToDevice);

    for (int i = 0; i < LNUM; i++) {
        // LN1
        ln_kernel<<<ROWS, 256>>>(out, ln1_g + i*DIM, ln1_b + i*DIM, h);
        // QKV: [8192,256] x [256,6144] -> scatter q/k/v [b,h,n,d]
        gemm_tc<EPI_QKV, false><<<dim3(3*HID/128, ROWS/128, 1), 256>>>(
            h, rqkvw + (long)i*DIM*3*HID, qkv_b + (long)i*3*HID,
            q, k, v, 3*HID, DIM, 0, 0, 0);
        // scores = q @ k^T, batched over 64 (b,h)
        gemm_tc<EPI_STORE, true><<<dim3(SEQ/128, SEQ/128, BH), 256>>>(
            q, k, nullptr, s, nullptr, nullptr,
            SEQ, DIM, (long)SEQ*DIM, (long)SEQ*DIM, (long)SEQ*SEQ);
        // softmax + /16 (+ tf32 round)
        softmax_kernel<<<BH*SEQ, 256>>>(s);
        // o = attn @ v, batched; scatter into [b,n,h*d]
        gemm_tc<EPI_OSCAT, false><<<dim3(DIM/128, SEQ/128, BH), 256>>>(
            s, v, nullptr, o, nullptr, nullptr,
            DIM, SEQ, (long)SEQ*SEQ, (long)SEQ*DIM, 0);
        // x += o @ proj_w + proj_b
        gemm_tc<EPI_BIAS_RES, false><<<dim3(DIM/128, ROWS/128, 1), 256>>>(
            o, rprojw + (long)i*HID*DIM, proj_b + (long)i*DIM,
            out, nullptr, nullptr, DIM, HID, 0, 0, 0);
        // LN2
        ln_kernel<<<ROWS, 256>>>(out, ln2_g + i*DIM, ln2_b + i*DIM, h);
        // mlp hidden = gelu(h @ w1 + b1)
        gemm_tc<EPI_BIAS_GELU, false><<<dim3(MLP/128, ROWS/128, 1), 256>>>(
            h, rw1 + (long)i*DIM*MLP, b1 + (long)i*MLP,
            mh, nullptr, nullptr, MLP, DIM, 0, 0, 0);
        // x += mh @ w2 + b2
        gemm_tc<EPI_BIAS_RES, false><<<dim3(DIM/128, ROWS/128, 1), 256>>>(
            mh, rw2 + (long)i*MLP*DIM, b2 + (long)i*DIM,
            out, nullptr, nullptr, DIM, MLP, 0, 0, 0);
    }
}

// round 5
// speedup vs baseline: 2.5855x; 1.1281x over previous
#include <cuda_runtime.h>
#include <math.h>

#define LNUM 4
#define DIM 256
#define NH 8
#define MLP 1024
#define BATCH 8
#define SEQ 1024
#define HID 2048            // NH * DIM
#define ROWS (BATCH*SEQ)    // 8192
#define BH (BATCH*NH)       // 64

// ---------------- scratch (device globals; no allocation allowed) ----------------
__device__ float g_h[ROWS*DIM];            // LN output (k-permuted)      8 MB
__device__ float g_q[BH*SEQ*DIM];          // q [b,h,n,d']                8 MB
__device__ float g_k[BH*SEQ*DIM];          // k [b,h,n,d']                8 MB
__device__ float g_v[BH*DIM*SEQ];          // v TRANSPOSED [b,h,d,n']     8 MB
__device__ float g_s[(size_t)BH*SEQ*SEQ];  // scores (cols permuted)    256 MB
__device__ float g_o[(size_t)ROWS*HID];    // attn out [b,n,(h d)']      64 MB
__device__ float g_m[ROWS*MLP];            // mlp hidden (permuted)      32 MB
// transposed + tf32-rounded + k-permuted weights
__device__ float g_qkvw[LNUM*DIM*3*HID];   // [l][6144][256']            25 MB
__device__ float g_projw[LNUM*HID*DIM];    // [l][256][2048']             8 MB
__device__ float g_w1[LNUM*DIM*MLP];       // [l][1024][256']             4 MB
__device__ float g_w2[LNUM*MLP*DIM];       // [l][256][1024']             4 MB

__device__ __forceinline__ float f2tf32(float x) {
    unsigned y;
    asm("cvt.rna.tf32.f32 %0, %1;" : "=r"(y) : "f"(x));
    return __uint_as_float(y);
}
// k-permutation within each 8-block: fragment pairs (tig, tig+4) become adjacent
__device__ __forceinline__ int p8(int i) {
    return (i & ~7) | (((i & 3) << 1) | ((i >> 2) & 1));
}

// ---------------- weight preprocess: transpose [K][N]->[N][K'], round tf32 ------
__global__ void wtrans_kernel(const float* __restrict__ src, float* __restrict__ dst,
                              int K, int N)
{
    __shared__ float tile[32][33];
    long zo = (long)blockIdx.z * K * N;
    int k0 = blockIdx.y * 32, n0 = blockIdx.x * 32;
    for (int i = threadIdx.y; i < 32; i += 8)
        tile[i][threadIdx.x] = src[zo + (long)(k0 + i)*N + n0 + threadIdx.x];
    __syncthreads();
    int k = k0 + threadIdx.x;
    int kp = p8(k);
    for (int i = threadIdx.y; i < 32; i += 8)
        dst[zo + (long)(n0 + i)*K + kp] = f2tf32(tile[threadIdx.x][i]);
}

// ---------------- LayerNorm: one block (256 thr) per row; writes permuted -------
__global__ void ln_kernel(const float* __restrict__ x, const float* __restrict__ g,
                          const float* __restrict__ b, float* __restrict__ out)
{
    __shared__ float red0[8], red1[8];
    __shared__ float mv0, mv1;
    int row = blockIdx.x;
    int t = threadIdx.x;
    float val = x[(long)row*DIM + t];
    float s1 = val, s2 = val*val;
    #pragma unroll
    for (int o = 16; o > 0; o >>= 1) {
        s1 += __shfl_xor_sync(0xffffffffu, s1, o);
        s2 += __shfl_xor_sync(0xffffffffu, s2, o);
    }
    if ((t & 31) == 0) { red0[t>>5] = s1; red1[t>>5] = s2; }
    __syncthreads();
    if (t == 0) {
        float a = 0.f, c = 0.f;
        #pragma unroll
        for (int i = 0; i < 8; i++) { a += red0[i]; c += red1[i]; }
        float m = a * (1.0f/DIM);
        mv0 = m;
        mv1 = rsqrtf(c * (1.0f/DIM) - m*m + 1e-5f);
    }
    __syncthreads();
    out[(long)row*DIM + p8(t)] = f2tf32((val - mv0) * mv1 * g[t] + b[t]);
}

// ---------------- Softmax rows of 1024 then /16 (permutation-invariant) ---------
__global__ void softmax_kernel(float* __restrict__ s)
{
    __shared__ float red[8];
    __shared__ float bc;
    long base = (long)blockIdx.x * SEQ;
    int t = threadIdx.x;
    float4 v = *(const float4*)(s + base + t*4);
    float mx = fmaxf(fmaxf(v.x, v.y), fmaxf(v.z, v.w));
    #pragma unroll
    for (int o = 16; o > 0; o >>= 1) mx = fmaxf(mx, __shfl_xor_sync(0xffffffffu, mx, o));
    if ((t & 31) == 0) red[t>>5] = mx;
    __syncthreads();
    if (t == 0) {
        float m = red[0];
        #pragma unroll
        for (int i = 1; i < 8; i++) m = fmaxf(m, red[i]);
        bc = m;
    }
    __syncthreads();
    float m = bc;
    __syncthreads();
    v.x = expf(v.x - m); v.y = expf(v.y - m); v.z = expf(v.z - m); v.w = expf(v.w - m);
    float sm = v.x + v.y + v.z + v.w;
    #pragma unroll
    for (int o = 16; o > 0; o >>= 1) sm += __shfl_xor_sync(0xffffffffu, sm, o);
    if ((t & 31) == 0) red[t>>5] = sm;
    __syncthreads();
    if (t == 0) {
        float a = 0.f;
        #pragma unroll
        for (int i = 0; i < 8; i++) a += red[i];
        bc = a;
    }
    __syncthreads();
    float inv = 1.0f / (bc * 16.0f);   // post-softmax /sqrt(256)
    v.x = f2tf32(v.x * inv); v.y = f2tf32(v.y * inv);
    v.z = f2tf32(v.z * inv); v.w = f2tf32(v.w * inv);
    *(float4*)(s + base + t*4) = v;
}

// ---------------- tf32 TC GEMM: all operands [rows][k'] (TB form) ---------------
// C[m][n] = sum_k A[m][k'] B[n][k'].  Block 128x128, 256 thr, warp 32x64.
// cp.async double-buffered; fragment loads are conflict-free LDS.64.
enum { EPI_STORE = 0, EPI_QKV = 1, EPI_BIAS_RES = 2, EPI_BIAS_GELU = 3, EPI_OSCAT = 4 };

__device__ __forceinline__ void mma_tf32(float* d, float a0, float a1, float a2, float a3,
                                         float b0, float b1) {
    asm volatile(
        "mma.sync.aligned.m16n8k8.row.col.f32.tf32.tf32.f32 "
        "{%0,%1,%2,%3}, {%4,%5,%6,%7}, {%8,%9}, {%0,%1,%2,%3};"
        : "+f"(d[0]), "+f"(d[1]), "+f"(d[2]), "+f"(d[3])
        : "r"(__float_as_uint(a0)), "r"(__float_as_uint(a1)),
          "r"(__float_as_uint(a2)), "r"(__float_as_uint(a3)),
          "r"(__float_as_uint(b0)), "r"(__float_as_uint(b1)));
}

__device__ __forceinline__ void cpa16(unsigned d, const float* s) {
    asm volatile("cp.async.ca.shared.global [%0], [%1], 16;" :: "r"(d), "l"(s));
}

#define KS 24              // smem row stride (floats): banks {0,8,16,24} per gid
#define TSZ (128*KS)       // one stage of one operand

template<int EPI>
__global__ __launch_bounds__(256, 2)
void gemm_tc(const float* __restrict__ A, const float* __restrict__ Bm,
             const float* __restrict__ bias, float* __restrict__ Cp,
             float* __restrict__ P1, float* __restrict__ P2,
             int Nc, int K, long sA, long sB, long sC)
{
    __shared__ float As[2][TSZ];
    __shared__ float Bs[2][TSZ];

    int z  = blockIdx.z;
    int m0 = blockIdx.y * 128;
    int n0 = blockIdx.x * 128;
    int t    = threadIdx.x;
    int lane = t & 31;
    int warp = t >> 5;
    int wm = (warp >> 1) * 32;
    int wn = (warp & 1) * 64;
    int gid = lane >> 2;
    int tig = lane & 3;

    int ar = t >> 1, ac = (t & 1) * 8;
    const float* apg = A + (long)z*sA + (long)(m0 + ar)*K + ac;
    const float* bpg = Bm + (long)z*sB + (long)(n0 + ar)*K + ac;
    unsigned asb = (unsigned)__cvta_generic_to_shared(&As[0][0]);
    unsigned bsb = (unsigned)__cvta_generic_to_shared(&Bs[0][0]);
    unsigned ad0 = asb + (unsigned)(ar*KS + ac)*4u;
    unsigned bd0 = bsb + (unsigned)(ar*KS + ac)*4u;

    float acc[2][8][4];
    #pragma unroll
    for (int mt = 0; mt < 2; mt++)
        #pragma unroll
        for (int nt = 0; nt < 8; nt++)
            #pragma unroll
            for (int p = 0; p < 4; p++) acc[mt][nt][p] = 0.f;

    // prologue: stage 0
    cpa16(ad0, apg);  cpa16(ad0 + 16, apg + 4);
    cpa16(bd0, bpg);  cpa16(bd0 + 16, bpg + 4);
    asm volatile("cp.async.commit_group;");

    int niter = K / 16;
    for (int iter = 0; iter < niter; iter++) {
        int s = iter & 1;
        if (iter + 1 < niter) {
            int k0 = (iter + 1) * 16;
            unsigned ad = ad0 + (unsigned)((s^1)*TSZ)*4u;
            unsigned bd = bd0 + (unsigned)((s^1)*TSZ)*4u;
            cpa16(ad, apg + k0);  cpa16(ad + 16, apg + k0 + 4);
            cpa16(bd, bpg + k0);  cpa16(bd + 16, bpg + k0 + 4);
            asm volatile("cp.async.commit_group;");
            asm volatile("cp.async.wait_group 1;");
        } else {
            asm volatile("cp.async.wait_group 0;");
        }
        __syncthreads();

        const float* Asb = &As[s][0];
        const float* Bsb = &Bs[s][0];
        #pragma unroll
        for (int kk = 0; kk < 16; kk += 8) {
            // a fragments: lo = {a0,a2} @ row r; hi = {a1,a3} @ row r+8
            float2 alo[2], ahi[2], bf[8];
            #pragma unroll
            for (int mt = 0; mt < 2; mt++) {
                int r = wm + mt*16 + gid;
                alo[mt] = *(const float2*)&Asb[r*KS + kk + 2*tig];
                ahi[mt] = *(const float2*)&Asb[(r+8)*KS + kk + 2*tig];
            }
            #pragma unroll
            for (int nt = 0; nt < 8; nt++) {
                int c = wn + nt*8 + gid;
                bf[nt] = *(const float2*)&Bsb[c*KS + kk + 2*tig];
            }
            #pragma unroll
            for (int mt = 0; mt < 2; mt++)
                #pragma unroll
                for (int nt = 0; nt < 8; nt++)
                    mma_tf32(acc[mt][nt], alo[mt].x, ahi[mt].x, alo[mt].y, ahi[mt].y,
                             bf[nt].x, bf[nt].y);
        }
        __syncthreads();
    }

    // ---------------- epilogue ----------------
    #pragma unroll
    for (int mt = 0; mt < 2; mt++) {
        #pragma unroll
        for (int nt = 0; nt < 8; nt++) {
            #pragma unroll
            for (int p = 0; p < 4; p++) {
                int row = m0 + wm + mt*16 + gid + ((p >= 2) ? 8 : 0);
                int col = n0 + wn + nt*8 + 2*tig + (p & 1);
                float v = acc[mt][nt][p];
                if (EPI == EPI_STORE) {        // scores: permute cols (k of PV)
                    Cp[(long)z*sC + (long)row*Nc + p8(col)] = v;
                } else if (EPI == EPI_QKV) {
                    v += bias[col];
                    int si = col % 3;
                    int dc = (col / 3) & (DIM - 1);
                    int h  = col / (3*DIM);
                    int b  = row >> 10, n = row & (SEQ - 1);
                    if (si == 2) {             // v transposed: [b,h,d,n']
                        P2[(((long)(b*NH + h))*DIM + dc)*SEQ + p8(n)] = f2tf32(v);
                    } else {                   // q/k: [b,h,n,d']
                        float* dst = (si == 0) ? Cp : P1;
                        dst[(((long)(b*NH + h))*SEQ + n)*DIM + p8(dc)] = f2tf32(v);
                    }
                } else if (EPI == EPI_BIAS_RES) {   // residual: logical layout
                    Cp[(long)row*Nc + col] += v + bias[col];
                } else if (EPI == EPI_BIAS_GELU) {  // mlp hidden: permuted
                    float u = v + bias[col];
                    Cp[(long)row*Nc + p8(col)] = f2tf32(0.5f * u * (1.0f + erff(u * 0.70710678118654752f)));
                } else {                            // EPI_OSCAT: o permuted
                    int b = z >> 3, h = z & 7;
                    Cp[((long)(b*SEQ + row))*HID + h*DIM + p8(col)] = f2tf32(v);
                }
            }
        }
    }
}

// ---------------- host orchestration ----------------
extern "C" void kernel_launch(void* const* d_in, const int* in_sizes, int n_in,
                              void* d_out, int out_size)
{
    const float* x_in  = (const float*)d_in[0];
    const float* ln1_g = (const float*)d_in[1];
    const float* ln1_b = (const float*)d_in[2];
    const float* qkv_w = (const float*)d_in[3];
    const float* qkv_b = (const float*)d_in[4];
    const float* proj_w= (const float*)d_in[5];
    const float* proj_b= (const float*)d_in[6];
    const float* ln2_g = (const float*)d_in[7];
    const float* ln2_b = (const float*)d_in[8];
    const float* w1    = (const float*)d_in[9];
    const float* b1    = (const float*)d_in[10];
    const float* w2    = (const float*)d_in[11];
    const float* b2    = (const float*)d_in[12];
    float* out = (float*)d_out;

    float *h, *q, *k, *v, *s, *o, *mh, *rqkvw, *rprojw, *rw1, *rw2;
    cudaGetSymbolAddress((void**)&h,  g_h);
    cudaGetSymbolAddress((void**)&q,  g_q);
    cudaGetSymbolAddress((void**)&k,  g_k);
    cudaGetSymbolAddress((void**)&v,  g_v);
    cudaGetSymbolAddress((void**)&s,  g_s);
    cudaGetSymbolAddress((void**)&o,  g_o);
    cudaGetSymbolAddress((void**)&mh, g_m);
    cudaGetSymbolAddress((void**)&rqkvw, g_qkvw);
    cudaGetSymbolAddress((void**)&rprojw, g_projw);
    cudaGetSymbolAddress((void**)&rw1, g_w1);
    cudaGetSymbolAddress((void**)&rw2, g_w2);

    // preprocess weights: transpose to [N][K'], round to tf32
    dim3 tb(32, 8);
    wtrans_kernel<<<dim3(3*HID/32, DIM/32, LNUM), tb>>>(qkv_w,  rqkvw,  DIM, 3*HID);
    wtrans_kernel<<<dim3(DIM/32, HID/32, LNUM), tb>>>(proj_w, rprojw, HID, DIM);
    wtrans_kernel<<<dim3(MLP/32, DIM/32, LNUM), tb>>>(w1, rw1, DIM, MLP);
    wtrans_kernel<<<dim3(DIM/32, MLP/32, LNUM), tb>>>(w2, rw2, MLP, DIM);

    cudaMemcpyAsync(out, x_in, sizeof(float)*(size_t)ROWS*DIM, cudaMemcpyDeviceToDevice);

    for (int i = 0; i < LNUM; i++) {
        // LN1 -> h (k')
        ln_kernel<<<ROWS, 256>>>(out, ln1_g + i*DIM, ln1_b + i*DIM, h);
        // QKV: h [8192][256'] x qkvwT [6144][256'] -> scatter q/k/v
        gemm_tc<EPI_QKV><<<dim3(3*HID/128, ROWS/128, 1), 256>>>(
            h, rqkvw + (long)i*DIM*3*HID, qkv_b + (long)i*3*HID,
            q, k, v, 3*HID, DIM, 0, 0, 0);
        // scores = q @ k^T (both [n][d']), cols written permuted
        gemm_tc<EPI_STORE><<<dim3(SEQ/128, SEQ/128, BH), 256>>>(
            q, k, nullptr, s, nullptr, nullptr,
            SEQ, DIM, (long)SEQ*DIM, (long)SEQ*DIM, (long)SEQ*SEQ);
        // softmax + /16 (+ tf32 round); oblivious to col permutation
        softmax_kernel<<<BH*SEQ, 256>>>(s);
        // o = P @ V: A = s [q][s'], B = v [d][s']; scatter o [b,n,(h d)']
        gemm_tc<EPI_OSCAT><<<dim3(DIM/128, SEQ/128, BH), 256>>>(
            s, v, nullptr, o, nullptr, nullptr,
            DIM, SEQ, (long)SEQ*SEQ, (long)DIM*SEQ, 0);
        // x += o @ proj_w + proj_b (o [m][2048'], projT [256][2048'])
        gemm_tc<EPI_BIAS_RES><<<dim3(DIM/128, ROWS/128, 1), 256>>>(
            o, rprojw + (long)i*HID*DIM, proj_b + (long)i*DIM,
            out, nullptr, nullptr, DIM, HID, 0, 0, 0);
        // LN2 -> h (k')
        ln_kernel<<<ROWS, 256>>>(out, ln2_g + i*DIM, ln2_b + i*DIM, h);
        // mh = gelu(h @ w1 + b1)  (w1T [1024][256'])
        gemm_tc<EPI_BIAS_GELU><<<dim3(MLP/128, ROWS/128, 1), 256>>>(
            h, rw1 + (long)i*DIM*MLP, b1 + (long)i*MLP,
            mh, nullptr, nullptr, MLP, DIM, 0, 0, 0);
        // x += mh @ w2 + b2  (mh [m][1024'], w2T [256][1024'])
        gemm_tc<EPI_BIAS_RES><<<dim3(DIM/128, ROWS/128, 1), 256>>>(
            mh, rw2 + (long)i*MLP*DIM, b2 + (long)i*DIM,
            out, nullptr, nullptr, DIM, MLP, 0, 0, 0);
    }
}